// round 1
// baseline (speedup 1.0000x reference)
#include <cuda_runtime.h>
#include <cuda_bf16.h>

// Problem constants
#define Bt 64      // graphs
#define Nn 1024    // nodes per graph
#define Fd 128     // nfeat
#define Hd 256     // nhid

// ---------------- scratch (device globals: no runtime allocation allowed) ----
__device__ float g_T0[(size_t)Bt * Nn * Fd];   // adj @ embs          [B,N,F]  33.5 MB
__device__ float g_h1[(size_t)Bt * Nn * Hd];   // relu(T0@W0 + b0)    [B,N,H]  67 MB
__device__ float g_U [(size_t)Bt * Nn * Hd];   // h1 @ W1             [B,N,H]  67 MB
__device__ float g_h2[(size_t)Bt * Nn * Hd];   // relu(adj@U + b1)    [B,N,H]  67 MB
__device__ float g_vp[(size_t)Bt * 8 * Hd];    // partial row-0 mixes

// ---------------- generic tiled SGEMM: C[b] = A[b] @ B[b] (+bias, relu) -----
// A: M x K row-major, B: K x N row-major, C: M x N row-major.
// Batch strides in elements; stride 0 => shared operand across batch.
// Requires M%BM==0, N%BN==0, K%BK==0 (all true for our shapes).
template <int BM, int BN, int BK, int TM, int TN>
__global__ __launch_bounds__(256, 1)
void sgemm_kernel(const float* __restrict__ A, size_t sA,
                  const float* __restrict__ B, size_t sB,
                  float* __restrict__ C, size_t sC,
                  int M, int N, int K,
                  const float* __restrict__ bias, int doRelu)
{
    __shared__ float As[BK][BM];
    __shared__ float Bs[BK][BN];

    const int b = blockIdx.z;
    A += (size_t)b * sA;
    B += (size_t)b * sB;
    C += (size_t)b * sC;

    const int cRow = blockIdx.y * BM;
    const int cCol = blockIdx.x * BN;
    const int tid  = threadIdx.x;

    // 16x16 thread grid over the 128x128 tile
    const int tRow = (tid / (BN / TN)) * TM;
    const int tCol = (tid % (BN / TN)) * TN;

    // global-load mapping (float4)
    const int aRow = tid / (BK / 4);        // BK=8 -> tid/2 in [0,128)
    const int aCol = (tid % (BK / 4)) * 4;
    const int bRow = tid / (BN / 4);        // BN=128 -> tid/32 in [0,8)
    const int bCol = (tid % (BN / 4)) * 4;

    const float* Aptr = A + (size_t)(cRow + aRow) * K + aCol;
    const float* Bptr = B + (size_t)bRow * N + (cCol + bCol);

    float acc[TM][TN];
    #pragma unroll
    for (int i = 0; i < TM; i++)
        #pragma unroll
        for (int j = 0; j < TN; j++) acc[i][j] = 0.f;

    for (int k0 = 0; k0 < K; k0 += BK) {
        float4 av = *reinterpret_cast<const float4*>(Aptr + k0);
        As[aCol + 0][aRow] = av.x;
        As[aCol + 1][aRow] = av.y;
        As[aCol + 2][aRow] = av.z;
        As[aCol + 3][aRow] = av.w;
        float4 bv = *reinterpret_cast<const float4*>(Bptr + (size_t)k0 * N);
        *reinterpret_cast<float4*>(&Bs[bRow][bCol]) = bv;
        __syncthreads();

        #pragma unroll
        for (int kk = 0; kk < BK; kk++) {
            float ar[TM], br[TN];
            #pragma unroll
            for (int i = 0; i < TM; i++) ar[i] = As[kk][tRow + i];
            #pragma unroll
            for (int j = 0; j < TN; j++) br[j] = Bs[kk][tCol + j];
            #pragma unroll
            for (int i = 0; i < TM; i++)
                #pragma unroll
                for (int j = 0; j < TN; j++)
                    acc[i][j] = fmaf(ar[i], br[j], acc[i][j]);
        }
        __syncthreads();
    }

    // epilogue: optional bias (per-column) + relu, vectorized stores
    #pragma unroll
    for (int i = 0; i < TM; i++) {
        const int r = cRow + tRow + i;
        #pragma unroll
        for (int j = 0; j < TN; j += 4) {
            float4 o;
            o.x = acc[i][j + 0];
            o.y = acc[i][j + 1];
            o.z = acc[i][j + 2];
            o.w = acc[i][j + 3];
            if (bias) {
                const int c = cCol + tCol + j;
                o.x += bias[c + 0]; o.y += bias[c + 1];
                o.z += bias[c + 2]; o.w += bias[c + 3];
            }
            if (doRelu) {
                o.x = fmaxf(o.x, 0.f); o.y = fmaxf(o.y, 0.f);
                o.z = fmaxf(o.z, 0.f); o.w = fmaxf(o.w, 0.f);
            }
            *reinterpret_cast<float4*>(C + (size_t)r * N + cCol + tCol + j) = o;
        }
    }
}

// ---------------- layer-3 row-0 mix: vp[b,c,h] = sum_{n in chunk c} adj[b,0,n] * h2[b,n,h]
__global__ void rowmix_kernel(const float* __restrict__ adj,
                              const float* __restrict__ h2,
                              float* __restrict__ vp)
{
    const int c = blockIdx.x;     // 8 chunks of 128 nodes
    const int b = blockIdx.y;
    const int h = threadIdx.x;    // 256 threads (one per hidden unit)

    const float* ar = adj + (size_t)b * Nn * Nn + c * 128;
    const float* hb = h2  + (size_t)b * Nn * Hd + (size_t)(c * 128) * Hd;

    float acc = 0.f;
    #pragma unroll 8
    for (int n = 0; n < 128; n++)
        acc = fmaf(ar[n], hb[(size_t)n * Hd + h], acc);

    vp[((size_t)b * 8 + c) * Hd + h] = acc;
}

// ---------------- head: v -> relu(v@W2+b2) -> @Wl + bl -> out[b,:]
__global__ void head_kernel(const float* __restrict__ vp,
                            const float* __restrict__ W2,
                            const float* __restrict__ b2,
                            const float* __restrict__ Wl,
                            const float* __restrict__ bl,
                            float* __restrict__ out)
{
    const int b   = blockIdx.x;
    const int tid = threadIdx.x;   // 256 threads

    __shared__ float vsh[Hd];
    __shared__ float tsh[Hd];

    // reduce the 8 partials
    float acc = 0.f;
    #pragma unroll
    for (int c = 0; c < 8; c++)
        acc += vp[((size_t)b * 8 + c) * Hd + tid];
    vsh[tid] = acc;
    __syncthreads();

    // t = relu(v @ W2 + b2)
    float t = b2[tid];
    #pragma unroll 8
    for (int k = 0; k < Hd; k++)
        t = fmaf(vsh[k], W2[(size_t)k * Hd + tid], t);
    tsh[tid] = fmaxf(t, 0.f);
    __syncthreads();

    // out = t @ Wl + bl
    if (tid < Fd) {
        float o = bl[tid];
        #pragma unroll 8
        for (int h = 0; h < Hd; h++)
            o = fmaf(tsh[h], Wl[(size_t)h * Fd + tid], o);
        out[(size_t)b * Fd + tid] = o;
    }
}

// ---------------------------------------------------------------------------
extern "C" void kernel_launch(void* const* d_in, const int* in_sizes, int n_in,
                              void* d_out, int out_size)
{
    const float* embs = (const float*)d_in[0];   // [B,N,F]
    const float* adj  = (const float*)d_in[1];   // [B,N,N]
    const float* W0   = (const float*)d_in[2];   // [F,H]
    const float* b0   = (const float*)d_in[3];   // [H]
    const float* W1   = (const float*)d_in[4];   // [H,H]
    const float* b1   = (const float*)d_in[5];   // [H]
    const float* W2   = (const float*)d_in[6];   // [H,H]
    const float* b2   = (const float*)d_in[7];   // [H]
    const float* Wl   = (const float*)d_in[8];   // [H,F]
    const float* bl   = (const float*)d_in[9];   // [F]
    float* out = (float*)d_out;                  // [B,F]

    float *T0, *h1, *U, *h2, *vp;
    cudaGetSymbolAddress((void**)&T0, g_T0);
    cudaGetSymbolAddress((void**)&h1, g_h1);
    cudaGetSymbolAddress((void**)&U,  g_U);
    cudaGetSymbolAddress((void**)&h2, g_h2);
    cudaGetSymbolAddress((void**)&vp, g_vp);

    dim3 blk(256);

    // G0: T0 = adj @ embs        [1024x1024]@[1024x128]
    sgemm_kernel<128,128,8,8,8><<<dim3(Fd/128, Nn/128, Bt), blk>>>(
        adj, (size_t)Nn * Nn, embs, (size_t)Nn * Fd, T0, (size_t)Nn * Fd,
        Nn, Fd, Nn, nullptr, 0);

    // G1: h1 = relu(T0 @ W0 + b0)   [1024x128]@[128x256]
    sgemm_kernel<128,128,8,8,8><<<dim3(Hd/128, Nn/128, Bt), blk>>>(
        T0, (size_t)Nn * Fd, W0, 0, h1, (size_t)Nn * Hd,
        Nn, Hd, Fd, b0, 1);

    // G2: U = h1 @ W1               [1024x256]@[256x256]
    sgemm_kernel<128,128,8,8,8><<<dim3(Hd/128, Nn/128, Bt), blk>>>(
        h1, (size_t)Nn * Hd, W1, 0, U, (size_t)Nn * Hd,
        Nn, Hd, Hd, nullptr, 0);

    // G3: h2 = relu(adj @ U + b1)   [1024x1024]@[1024x256]
    sgemm_kernel<128,128,8,8,8><<<dim3(Hd/128, Nn/128, Bt), blk>>>(
        adj, (size_t)Nn * Nn, U, (size_t)Nn * Hd, h2, (size_t)Nn * Hd,
        Nn, Hd, Nn, b1, 1);

    // G4: vp[b,c,:] = adj[b,0,chunk c] @ h2[b,chunk c,:]
    rowmix_kernel<<<dim3(8, Bt), dim3(Hd)>>>(adj, h2, vp);

    // G5: out = relu(v@W2+b2) @ Wl + bl
    head_kernel<<<dim3(Bt), dim3(Hd)>>>(vp, W2, b2, Wl, bl, out);
}